// round 15
// baseline (speedup 1.0000x reference)
#include <cuda_runtime.h>
#include <math.h>

// ---------------------------------------------------------------------------
// Persistent single-kernel Gauss-Newton solver for the bi-exponential fit.
// R15:
//  - Phase 0: GN on the FIRST QUARTER of the data (mu scaled 0.25) until its
//    own convergence cliff (~1.7us/pass). Phase 1: same iteration on the full
//    data from that warm start (~3us/pass, expected 2-3 passes). The output
//    is the full-data fixed point under the same stop test as before.
//  - 20 fma-ops/point sweep: ex2 with folded log2e, 2-FFMA residual, and
//    raw-moment accumulation in the (e0,e1,t*e0,t*e1) basis (14 stats; the
//    c0/c1 factors are applied after the reduction; e1*te0 == e0*te1 dedup).
//  - Everything else from R14: fused Armijo (1 grid_sync/pass), acq/rel
//    barrier, float Cholesky, parity double-buffered transposed partials.
// ---------------------------------------------------------------------------

#define MAXB 384
#define NTHR 1024
#define NW   (NTHR / 32)
#define NSTAT 14
#define LOG2E 1.4426950408889634f

// ---- cross-block state ----------------------------------------------------
__device__ unsigned        g_bar_cnt = 0;
__device__ unsigned        g_bar_gen = 0;
__device__ volatile float  g_part[2][NSTAT][MAXB];  // [parity][stat][block]

// ---- acquire/release software grid barrier --------------------------------
__device__ __forceinline__ void grid_sync(int nb) {
    __syncthreads();
    if (threadIdx.x == 0) {
        unsigned gen;
        asm volatile("ld.relaxed.gpu.u32 %0, [%1];"
                     : "=r"(gen) : "l"(&g_bar_gen) : "memory");
        unsigned ticket;
        asm volatile("atom.acq_rel.gpu.add.u32 %0, [%1], %2;"
                     : "=r"(ticket) : "l"(&g_bar_cnt), "r"(1u) : "memory");
        if (ticket == (unsigned)(nb - 1)) {
            asm volatile("st.relaxed.gpu.u32 [%0], %1;"
                         :: "l"(&g_bar_cnt), "r"(0u) : "memory");
            asm volatile("st.release.gpu.u32 [%0], %1;"
                         :: "l"(&g_bar_gen), "r"(gen + 1u) : "memory");
        } else {
            unsigned cur;
            do {
                asm volatile("ld.acquire.gpu.u32 %0, [%1];"
                             : "=r"(cur) : "l"(&g_bar_gen) : "memory");
            } while (cur == gen);
        }
    }
    __syncthreads();
}

__device__ __forceinline__ float warp_sum(float v) {
#pragma unroll
    for (int o = 16; o > 0; o >>= 1) v += __shfl_down_sync(0xffffffffu, v, o);
    return v;
}

__device__ __forceinline__ double warp_sum_d(double v) {
#pragma unroll
    for (int o = 16; o > 0; o >>= 1) v += __shfl_down_sync(0xffffffffu, v, o);
    return v;
}

// Deterministic block reduction of NSTAT partials -> g_part[par][j][block]
__device__ __forceinline__ void block_reduce_store(const float* s, int par) {
    __shared__ float red[NSTAT][NW];
    int lane = threadIdx.x & 31, w = threadIdx.x >> 5;
#pragma unroll
    for (int j = 0; j < NSTAT; j++) {
        float v = warp_sum(s[j]);
        if (lane == 0) red[j][w] = v;
    }
    __syncthreads();
    if (w == 0) {
#pragma unroll
        for (int j = 0; j < NSTAT; j++) {
            float v = warp_sum(red[j][lane]);   // NW == 32
            if (lane == 0) g_part[par][j][blockIdx.x] = v;
        }
    }
    __syncthreads();
}

// Every block reduces all partials itself (bit-identical across blocks).
__device__ __forceinline__ void cross_reduce(double* Sh, int nb, int par) {
    int lane = threadIdx.x & 31, w = threadIdx.x >> 5;
    if (w < NSTAT) {
        double a = 0.0;
        for (int b = lane; b < nb; b += 32) a += (double)g_part[par][w][b];
        a = warp_sum_d(a);
        if (lane == 0) Sh[w] = a;
    }
    __syncthreads();
}

__device__ __forceinline__ float ex2_(float a) {
    float r;
    asm("ex2.approx.f32 %0, %1;" : "=f"(r) : "f"(a));
    return r;
}

// softplus — bitwise-stable at the plateau (same path every pass)
__device__ __forceinline__ float sp_(float u) { return log1pf(ex2_(u * LOG2E)); }

__device__ __forceinline__ float dot4(const float* a) {
    return ((a[0] * a[0] + a[1] * a[1]) + a[2] * a[2]) + a[3] * a[3];
}

// 4x4 SPD solve via float Cholesky (H = J^T J + mu I, no pivoting needed).
__device__ __forceinline__ void chol_solve4(const float A[4][4],
                                            const float b[4], float x[4]) {
    float L[4][4];
#pragma unroll
    for (int k = 0; k < 4; k++) {
        float d = A[k][k];
#pragma unroll
        for (int j = 0; j < 4; j++) if (j < k) d -= L[k][j] * L[k][j];
        float lkk = sqrtf(d);
        L[k][k] = lkk;
        float inv = __fdividef(1.0f, lkk);
#pragma unroll
        for (int i = 0; i < 4; i++) if (i > k) {
            float s2 = A[i][k];
#pragma unroll
            for (int j = 0; j < 4; j++) if (j < k) s2 -= L[i][j] * L[k][j];
            L[i][k] = s2 * inv;
        }
    }
    float z[4];
#pragma unroll
    for (int i = 0; i < 4; i++) {
        float s2 = b[i];
#pragma unroll
        for (int j = 0; j < 4; j++) if (j < i) s2 -= L[i][j] * z[j];
        z[i] = __fdividef(s2, L[i][i]);
    }
#pragma unroll
    for (int i = 3; i >= 0; i--) {
        float s2 = z[i];
#pragma unroll
        for (int j = 0; j < 4; j++) if (j > i) s2 -= L[j][i] * x[j];
        x[i] = __fdividef(s2, L[i][i]);
    }
}

// Per-block solver state (identical contents in every block).
struct GNState {
    float ucand[4];   // point evaluated by the NEXT pass
    float uacc[4];    // last accepted point
    float du[4];      // current search direction
    float gd;         // grad . du at uacc
    float loss;       // accepted loss
    float step;       // step size of current candidate
    int   first;      // no accepted point in this phase yet
    int   force;      // 25 halvings exhausted -> accept unconditionally
    int   trial;      // halvings this iteration
    int   iter;       // accepted iterations this phase
    int   phase;      // 0 = quarter subsample, 1 = full data
    int   done;
};

__global__ void __launch_bounds__(NTHR, 1)
gn_kernel(const float* __restrict__ logmu_p,
          const float* __restrict__ y,
          const float* __restrict__ t,
          const float* __restrict__ x_init,
          float* __restrict__ out, int n, int nb) {
    const float mu_full = expf(logmu_p[0]);
    const int   gtid = blockIdx.x * NTHR + threadIdx.x;
    const int   strd = nb * NTHR;
    const int   n4   = n >> 2;
    const int   q4   = n4 >> 2;          // quarter of the data, in float4s
    const float4* __restrict__ t4 = (const float4*)t;
    const float4* __restrict__ y4 = (const float4*)y;

    __shared__ double  Sh[NSTAT];
    __shared__ GNState st;

    if (threadIdx.x == 0) {
        for (int i = 0; i < 4; i++) {
            float xi = fmaxf(x_init[i], 1e-3f);
            st.ucand[i] = logf(expf(xi) - 1.0f + 1e-8f);
            st.du[i] = 0.0f;
        }
        st.first = 1; st.force = 0; st.trial = 0; st.iter = 0;
        st.phase = 0;  st.done = 0;
        st.step = 0.0f; st.gd = 0.0f; st.loss = 0.0f;
    }
    __syncthreads();

    for (int pass = 0; pass < 400; pass++) {
        if (st.done) break;
        const int  par   = pass & 1;
        const int  phase = st.phase;
        // subsample problem uses mu scaled by its data fraction
        const float mu = phase ? mu_full : mu_full * 0.25f;

        float uc[4], x[4];
#pragma unroll
        for (int i = 0; i < 4; i++) { uc[i] = st.ucand[i]; x[i] = sp_(uc[i]); }
        const float c0  = x[0], c1 = x[1];
        const float k0  = -x[2] * LOG2E;     // fold log2(e) into the rates
        const float k1  = -x[3] * LOG2E;
        const float nc0 = -c0, nc1 = -c1;

        // ---- 14 raw-moment statistics at the candidate point ----
        // basis (e0, e1, te0=t*e0, te1=t*e1); note e1*te0 == e0*te1.
        float s[NSTAT];
#pragma unroll
        for (int j = 0; j < NSTAT; j++) s[j] = 0.0f;

        auto acc_pt = [&](float ti, float yi) {
            float e0  = ex2_(k0 * ti);
            float e1  = ex2_(k1 * ti);
            float r   = __fmaf_rn(nc1, e1, __fmaf_rn(nc0, e0, yi));
            float te0 = ti * e0;
            float te1 = ti * e1;
            s[0]  = __fmaf_rn(e0,  e0,  s[0]);   // m00
            s[1]  = __fmaf_rn(e0,  e1,  s[1]);   // m01
            s[2]  = __fmaf_rn(e0,  te0, s[2]);   // m02
            s[3]  = __fmaf_rn(e0,  te1, s[3]);   // m03 (== m12)
            s[4]  = __fmaf_rn(e1,  e1,  s[4]);   // m11
            s[5]  = __fmaf_rn(e1,  te1, s[5]);   // m13
            s[6]  = __fmaf_rn(te0, te0, s[6]);   // m22
            s[7]  = __fmaf_rn(te0, te1, s[7]);   // m23
            s[8]  = __fmaf_rn(te1, te1, s[8]);   // m33
            s[9]  = __fmaf_rn(e0,  r,   s[9]);   // v0
            s[10] = __fmaf_rn(e1,  r,   s[10]);  // v1
            s[11] = __fmaf_rn(te0, r,   s[11]);  // v2
            s[12] = __fmaf_rn(te1, r,   s[12]);  // v3
            s[13] = __fmaf_rn(r,   r,   s[13]);  // rr
        };

        const int m4 = phase ? n4 : q4;
        for (int i = gtid; i < m4; i += strd) {
            float4 tv = t4[i], yv = y4[i];
            acc_pt(tv.x, yv.x); acc_pt(tv.y, yv.y);
            acc_pt(tv.z, yv.z); acc_pt(tv.w, yv.w);
        }
        if (phase) {
            for (int i = (n4 << 2) + gtid; i < n; i += strd)
                acc_pt(t[i], y[i]);
        }

        block_reduce_store(s, par);
        grid_sync(nb);
        cross_reduce(Sh, nb, par);

        // ---- fused Armijo test + GN solve (thread 0; identical per block) --
        if (threadIdx.x == 0) {
            float loss_c = (float)Sh[13] + mu * dot4(x);
            bool acc = st.first || st.force ||
                       (loss_c <= st.loss - 1e-4f * st.step * st.gd);
            if (acc) {
                float nn = ((st.du[0]*st.du[0] + st.du[1]*st.du[1])
                            + st.du[2]*st.du[2]) + st.du[3]*st.du[3];
                float upd = st.step * sqrtf(nn);
                float dec = st.loss - loss_c;
                bool stop = !st.first &&
                            ((upd < 1e-5f) ||
                             (dec < 1e-4f * fabsf(loss_c)) ||
                             (st.iter >= (phase ? 300 : 60)));
                for (int i = 0; i < 4; i++) st.uacc[i] = uc[i];
                st.loss = loss_c;
                st.iter++;
                if (stop) {
                    if (phase == 0) {
                        // switch to full data; re-enter at the warm start
                        st.phase = 1; st.first = 1; st.force = 0;
                        st.trial = 0; st.iter = 0;
                        for (int i = 0; i < 4; i++) st.ucand[i] = st.uacc[i];
                    } else {
                        st.done = 1;
                    }
                } else {
                    // assemble G = Jx^T Jx and Jx^T r from the raw moments
                    float m00 = (float)Sh[0], m01 = (float)Sh[1];
                    float m02 = (float)Sh[2], m03 = (float)Sh[3];
                    float m11 = (float)Sh[4], m13 = (float)Sh[5];
                    float m22 = (float)Sh[6], m23 = (float)Sh[7];
                    float m33 = (float)Sh[8];
                    float v0  = (float)Sh[9],  v1 = (float)Sh[10];
                    float v2  = (float)Sh[11], v3 = (float)Sh[12];
                    float G[4][4];
                    G[0][0] = m00;            G[0][1] = m01;
                    G[0][2] = -c0 * m02;      G[0][3] = -c1 * m03;
                    G[1][1] = m11;
                    G[1][2] = -c0 * m03;      G[1][3] = -c1 * m13;
                    G[2][2] = c0 * c0 * m22;  G[2][3] = c0 * c1 * m23;
                    G[3][3] = c1 * c1 * m33;
                    G[1][0] = G[0][1]; G[2][0] = G[0][2]; G[3][0] = G[0][3];
                    G[2][1] = G[1][2]; G[3][1] = G[1][3]; G[3][2] = G[2][3];
                    float JTr[4] = { v0, v1, -c0 * v2, -c1 * v3 };

                    float sd[4];
                    for (int i = 0; i < 4; i++)
                        sd[i] = 1.0f / (1.0f + ex2_(-uc[i] * LOG2E));
                    float H[4][4], grad[4], rhs[4], du[4];
                    for (int i = 0; i < 4; i++) {
                        for (int j = 0; j < 4; j++)
                            H[i][j] = G[i][j] * sd[i] * sd[j];
                        H[i][i] += mu + 1e-7f;
                        grad[i] = -(sd[i] * JTr[i]) + mu * x[i] * sd[i];
                        rhs[i]  = -grad[i];
                    }
                    chol_solve4(H, rhs, du);
                    float gd = 0.0f;
                    for (int i = 0; i < 4; i++) {
                        st.du[i] = du[i];
                        gd += grad[i] * du[i];
                    }
                    st.gd    = gd;
                    st.step  = 1.0f;
                    st.trial = 0;
                    st.first = 0;
                    st.force = 0;
                    for (int i = 0; i < 4; i++)
                        st.ucand[i] = uc[i] + du[i];
                }
            } else {
                // reject: halve the step, retry from the accepted point
                st.trial++;
                st.step *= 0.5f;
                if (st.trial >= 25) st.force = 1;
                for (int i = 0; i < 4; i++)
                    st.ucand[i] = st.uacc[i] + st.step * st.du[i];
            }
        }
        __syncthreads();
    }

    if (blockIdx.x == 0 && threadIdx.x == 0) {
        for (int i = 0; i < 4; i++) out[i] = sp_(st.uacc[i]);
    }
}

extern "C" void kernel_launch(void* const* d_in, const int* in_sizes, int n_in,
                              void* d_out, int out_size) {
    const float* logmu  = (const float*)d_in[0];
    const float* y      = (const float*)d_in[1];
    const float* t      = (const float*)d_in[2];
    const float* x_init = (const float*)d_in[3];
    float* out = (float*)d_out;
    int n = in_sizes[1];

    int dev = 0;
    cudaGetDevice(&dev);
    int sms = 0;
    cudaDeviceGetAttribute(&sms, cudaDevAttrMultiProcessorCount, dev);
    if (sms <= 0) sms = 148;

    // Deadlock-safe grid: only as many blocks as are guaranteed co-resident.
    int bpsm = 1;
    cudaOccupancyMaxActiveBlocksPerMultiprocessor(&bpsm, gn_kernel, NTHR, 0);
    if (bpsm < 1) bpsm = 1;
    if (bpsm > 2) bpsm = 2;

    int nb = sms * bpsm;
    if (nb > MAXB) nb = MAXB;

    gn_kernel<<<nb, NTHR>>>(logmu, y, t, x_init, out, n, nb);
}